// round 15
// baseline (speedup 1.0000x reference)
#include <cuda_runtime.h>
#include <cuda_fp16.h>
#include <math.h>
#include <stdint.h>

#define BATCH 8
#define LSEQ  4096
#define DMOD  256
#define DFF   512
#define NHEAD 8
#define HDIM  32
#define MROWS (BATCH * LSEQ)
#define KVCH  16
#define STG2  65536            /* stage: Ah 16K | Al 16K | B 32K */
#define GSMEM_W  (3 * STG2)
#define GSMEM_LN (3 * STG2 + 4096)
#define WLAYER 524288

__device__ float g_q [MROWS * DMOD];
__device__ float g_k [MROWS * DMOD];
__device__ float g_v [MROWS * DMOD];
__device__ float g_kv [BATCH * NHEAD * HDIM * HDIM];
__device__ float g_ks [BATCH * NHEAD * HDIM];
__device__ float g_kvp[BATCH * NHEAD * KVCH * HDIM * HDIM];
__device__ float g_ksp[BATCH * NHEAD * KVCH * HDIM];
__device__ __half g_xh [MROWS * DMOD];
__device__ __half g_xl [MROWS * DMOD];
__device__ __half g_p2h[MROWS * DMOD];
__device__ __half g_p2l[MROWS * DMOD];
__device__ __half g_mh [MROWS * DMOD];
__device__ __half g_ml [MROWS * DMOD];
__device__ __half g_hh [MROWS * DFF];
__device__ __half g_hl [MROWS * DFF];
__device__ __half g_wth[4 * WLAYER];

__device__ __forceinline__ uint32_t smem_u32(const void* p) {
    uint32_t a;
    asm("{ .reg .u64 t; cvta.to.shared.u64 t, %1; cvt.u32.u64 %0, t; }" : "=r"(a) : "l"(p));
    return a;
}
__device__ __forceinline__ uint32_t swz128(uint32_t off) { return off ^ ((off >> 3) & 0x70); }
__device__ __forceinline__ void cpa16(uint32_t dst, const void* src) {
    asm volatile("cp.async.cg.shared.global [%0], [%1], 16;" :: "r"(dst), "l"(src));
}
__device__ __forceinline__ void ldsm4(uint32_t* r, uint32_t a) {
    asm volatile("ldmatrix.sync.aligned.m8n8.x4.shared.b16 {%0,%1,%2,%3}, [%4];"
                 : "=r"(r[0]), "=r"(r[1]), "=r"(r[2]), "=r"(r[3]) : "r"(a));
}
__device__ __forceinline__ void mma16816(float* c, const uint32_t* a, uint32_t b0, uint32_t b1) {
    asm volatile(
        "mma.sync.aligned.m16n8k16.row.col.f32.f16.f16.f32 "
        "{%0,%1,%2,%3},{%4,%5,%6,%7},{%8,%9},{%0,%1,%2,%3};"
        : "+f"(c[0]), "+f"(c[1]), "+f"(c[2]), "+f"(c[3])
        : "r"(a[0]), "r"(a[1]), "r"(a[2]), "r"(a[3]), "r"(b0), "r"(b1));
}
__device__ __forceinline__ void split2h(float x, __half& h, __half& l) {
    h = __float2half_rn(x);
    l = __float2half_rn(x - __half2float(h));
}

__global__ void posenc_kernel(const float* __restrict__ ref, const float* __restrict__ src,
                              __half* __restrict__ p1h, __half* __restrict__ p1l,
                              __half* __restrict__ p2h, __half* __restrict__ p2l) {
    __shared__ float s[32][33];
    int img = blockIdx.y >> 2, n = blockIdx.y & 3;
    int ct = blockIdx.x >> 7, lt = blockIdx.x & 127;
    int c0 = ct * 32, l0 = lt * 32;
    int tid = threadIdx.x;
    const float* inp = (img == 0) ? ref : src;
#pragma unroll
    for (int p = 0; p < 4; p++) {
        int c = p * 8 + (tid >> 5), l = tid & 31;
        s[c][l] = inp[((size_t)n * DMOD + c0 + c) * LSEQ + l0 + l];
    }
    __syncthreads();
#pragma unroll
    for (int p = 0; p < 4; p++) {
        int l = p * 8 + (tid >> 5), c = tid & 31;
        int cg = c0 + c, lg = l0 + l;
        int ii = cg >> 2, jj = cg & 3;
        float dv = __expf(-(float)ii * (logf(10000.0f) / 64.0f));
        int w = lg & 63, hh = lg >> 6;
        float arg = (jj < 2 ? (float)w : (float)hh) * dv;
        float pe = (jj & 1) ? cosf(arg) : sinf(arg);
        float val = s[c][l] + pe;
        size_t o1 = ((size_t)(img * 4 + n) * LSEQ + lg) * DMOD + cg;
        size_t o2 = ((size_t)((1 - img) * 4 + n) * LSEQ + lg) * DMOD + cg;
        __half h, lo;
        split2h(val, h, lo);
        p1h[o1] = h; p1l[o1] = lo;
        p2h[o2] = h; p2l[o2] = lo;
    }
}

__global__ void wconv_all(const float* __restrict__ Wq, const float* __restrict__ Wk,
                          const float* __restrict__ Wv, const float* __restrict__ Wo,
                          const float* __restrict__ W1, const float* __restrict__ W2) {
    __shared__ float s[32][33];
    int li = blockIdx.x >> 9;
    int r  = blockIdx.x & 511;
    const float* src;
    size_t dsto;
    int K, N, n0, k0;
    if (r < 256) {
        int mat = r >> 6, t = r & 63;
        K = 256; N = 256;
        n0 = (t & 7) * 32; k0 = (t >> 3) * 32;
        const float* bases[4] = {Wq, Wk, Wv, Wo};
        src  = bases[mat] + (size_t)li * 65536;
        dsto = (size_t)li * WLAYER + (size_t)mat * 65536;
    } else if (r < 384) {
        int t = r - 256;
        K = 256; N = 512;
        n0 = (t & 15) * 32; k0 = (t >> 4) * 32;
        src  = W1 + (size_t)li * 131072;
        dsto = (size_t)li * WLAYER + 262144;
    } else {
        int t = r - 384;
        K = 512; N = 256;
        n0 = (t & 7) * 32; k0 = (t >> 3) * 32;
        src  = W2 + (size_t)li * 131072;
        dsto = (size_t)li * WLAYER + 393216;
    }
    int tid = threadIdx.x;
#pragma unroll
    for (int p = 0; p < 4; p++) {
        int kk = p * 8 + (tid >> 5), nn = tid & 31;
        s[kk][nn] = src[(size_t)(k0 + kk) * N + n0 + nn];
    }
    __syncthreads();
#pragma unroll
    for (int p = 0; p < 4; p++) {
        int nn = p * 8 + (tid >> 5), kk = tid & 31;
        g_wth[dsto + (size_t)(n0 + nn) * K + k0 + kk] = __float2half_rn(s[kk][nn]);
    }
}

// ---------------- shared load stage (128 A-rows, 256 B-rows) -------------------
__device__ __forceinline__ void load_stage_w(const __half* Ah, const __half* Al,
                                             const __half* Bh,
                                             int bm, int bn, int K, int k0,
                                             uint32_t sb, int tid) {
    {
        int r = tid >> 3, seg = tid & 7;
        uint32_t d = swz128((uint32_t)(r * 128 + seg * 16));
        size_t ga = (size_t)(bm + r) * K + k0 + seg * 8;
        cpa16(sb + d,         Ah + ga);
        cpa16(sb + 16384 + d, Al + ga);
    }
#pragma unroll
    for (int it = 0; it < 2; it++) {
        int c = tid + it * 1024;
        int r = c >> 3, seg = c & 7;
        uint32_t d = swz128((uint32_t)(r * 128 + seg * 16));
        cpa16(sb + 32768 + d, Bh + (size_t)(bn + r) * K + k0 + seg * 8);
    }
    asm volatile("cp.async.commit_group;" ::: "memory");
}

// ---------------- gemm_w: 128x256 tile, 1024 threads, 3-stage ------------------
// grid (M/128, N/256). mode: 0 fp32, 1 fp32+elu+1, 2 half-pair+relu
__global__ __launch_bounds__(1024, 1)
void gemm_w(const __half* __restrict__ Ah, const __half* __restrict__ Al,
            const __half* __restrict__ Bh,
            const float* __restrict__ bias,
            float* __restrict__ Cf, __half* __restrict__ Ch, __half* __restrict__ Cl,
            int N, int K, int mode) {
    extern __shared__ char smem[];
    uint32_t sb = smem_u32(smem);
    int tid = threadIdx.x, lane = tid & 31, warp = tid >> 5;
    int wm = warp >> 2, wn = warp & 3;       // 8m x 4n, warp tile 16x64
    int bm = blockIdx.x * 128, bn = blockIdx.y * 256;

    float acc[8][4];
#pragma unroll
    for (int j = 0; j < 8; j++)
#pragma unroll
        for (int r = 0; r < 4; r++) acc[j][r] = 0.0f;

    const int KT = K >> 6;
    load_stage_w(Ah, Al, Bh, bm, bn, K, 0, sb, tid);
    if (KT > 1) load_stage_w(Ah, Al, Bh, bm, bn, K, 64, sb + STG2, tid);

    int lrow = (lane & 7) + ((lane >> 3) & 1) * 8;
    int kseg = (lane >> 4) * 16;

    for (int kt = 0; kt < KT; kt++) {
        if (kt + 1 < KT) asm volatile("cp.async.wait_group 1;" ::: "memory");
        else             asm volatile("cp.async.wait_group 0;" ::: "memory");
        __syncthreads();
        if (kt + 2 < KT)
            load_stage_w(Ah, Al, Bh, bm, bn, K, (kt + 2) << 6, sb + ((kt + 2) % 3) * STG2, tid);

        uint32_t offA = sb + (kt % 3) * STG2;
        uint32_t offAl = offA + 16384, offB = offA + 32768;
#pragma unroll
        for (int kk = 0; kk < 4; kk++) {
            int kb = kk * 32 + kseg;
            uint32_t ah[4], al[4];
            {
                uint32_t off = swz128((uint32_t)((wm * 16 + lrow) * 128 + kb));
                ldsm4(ah, offA  + off);
                ldsm4(al, offAl + off);
            }
#pragma unroll
            for (int j = 0; j < 4; j++) {
                uint32_t bfr[4];
                uint32_t off = swz128((uint32_t)((wn * 64 + j * 16 + lrow) * 128 + kb));
                ldsm4(bfr, offB + off);
#pragma unroll
                for (int s = 0; s < 2; s++) {
                    int n8 = j * 2 + s;
                    mma16816(acc[n8], ah, bfr[s], bfr[2 + s]);
                    mma16816(acc[n8], al, bfr[s], bfr[2 + s]);
                }
            }
        }
    }
    __syncthreads();

    int gid = lane >> 2, tig = lane & 3;
#pragma unroll
    for (int n8 = 0; n8 < 8; n8++) {
        int col = bn + wn * 64 + n8 * 8 + tig * 2;
        float2 bv = *(const float2*)(bias + col);
#pragma unroll
        for (int half = 0; half < 2; half++) {
            int row = bm + wm * 16 + gid + half * 8;
            float v0 = acc[n8][half * 2 + 0] + bv.x;
            float v1 = acc[n8][half * 2 + 1] + bv.y;
            if (mode == 1) {
                v0 = (v0 > 0.f) ? v0 + 1.f : __expf(v0);
                v1 = (v1 > 0.f) ? v1 + 1.f : __expf(v1);
            } else if (mode == 2) {
                v0 = fmaxf(v0, 0.f);
                v1 = fmaxf(v1, 0.f);
            }
            if (mode == 2) {
                __half h0, l0, h1, l1;
                split2h(v0, h0, l0);
                split2h(v1, h1, l1);
                *(__half2*)(Ch + (size_t)row * N + col) = __halves2half2(h0, h1);
                *(__half2*)(Cl + (size_t)row * N + col) = __halves2half2(l0, l1);
            } else {
                *(float2*)(Cf + (size_t)row * N + col) = make_float2(v0, v1);
            }
        }
    }
}

// ---------------- gemm_ln: 128x256 tile, fused bias+residual+LayerNorm ---------
__global__ __launch_bounds__(1024, 1)
void gemm_ln(const __half* __restrict__ Ah, const __half* __restrict__ Al,
             const __half* __restrict__ Bh,
             const float* __restrict__ bias,
             const __half* __restrict__ Rh, const __half* __restrict__ Rl,
             const float* __restrict__ gamma, const float* __restrict__ beta,
             __half* __restrict__ Oh, __half* __restrict__ Ol,
             int K) {
    extern __shared__ char smem[];
    uint32_t sb = smem_u32(smem);
    float* redS = (float*)(smem + 3 * STG2);
    float* redQ = (float*)(smem + 3 * STG2 + 2048);
    int tid = threadIdx.x, lane = tid & 31, warp = tid >> 5;
    int wm = warp >> 2, wn = warp & 3;
    int bm = blockIdx.x * 128;

    float acc[8][4];
#pragma unroll
    for (int j = 0; j < 8; j++)
#pragma unroll
        for (int r = 0; r < 4; r++) acc[j][r] = 0.0f;

    const int KT = K >> 6;
    load_stage_w(Ah, Al, Bh, bm, 0, K, 0, sb, tid);
    if (KT > 1) load_stage_w(Ah, Al, Bh, bm, 0, K, 64, sb + STG2, tid);

    int lrow = (lane & 7) + ((lane >> 3) & 1) * 8;
    int kseg = (lane >> 4) * 16;

    for (int kt = 0; kt < KT; kt++) {
        if (kt + 1 < KT) asm volatile("cp.async.wait_group 1;" ::: "memory");
        else             asm volatile("cp.async.wait_group 0;" ::: "memory");
        __syncthreads();
        if (kt + 2 < KT)
            load_stage_w(Ah, Al, Bh, bm, 0, K, (kt + 2) << 6, sb + ((kt + 2) % 3) * STG2, tid);

        uint32_t offA = sb + (kt % 3) * STG2;
        uint32_t offAl = offA + 16384, offB = offA + 32768;
#pragma unroll
        for (int kk = 0; kk < 4; kk++) {
            int kb = kk * 32 + kseg;
            uint32_t ah[4], al[4];
            {
                uint32_t off = swz128((uint32_t)((wm * 16 + lrow) * 128 + kb));
                ldsm4(ah, offA  + off);
                ldsm4(al, offAl + off);
            }
#pragma unroll
            for (int j = 0; j < 4; j++) {
                uint32_t bfr[4];
                uint32_t off = swz128((uint32_t)((wn * 64 + j * 16 + lrow) * 128 + kb));
                ldsm4(bfr, offB + off);
#pragma unroll
                for (int s = 0; s < 2; s++) {
                    int n8 = j * 2 + s;
                    mma16816(acc[n8], ah, bfr[s], bfr[2 + s]);
                    mma16816(acc[n8], al, bfr[s], bfr[2 + s]);
                }
            }
        }
    }
    __syncthreads();

    int gid = lane >> 2, tig = lane & 3;
    float s0 = 0.f, q0 = 0.f, s1 = 0.f, q1 = 0.f;
#pragma unroll
    for (int n8 = 0; n8 < 8; n8++) {
        int col = wn * 64 + n8 * 8 + tig * 2;
        float2 bv = *(const float2*)(bias + col);
#pragma unroll
        for (int half = 0; half < 2; half++) {
            int row = bm + wm * 16 + gid + half * 8;
            __half2 rh = *(const __half2*)(Rh + (size_t)row * DMOD + col);
            __half2 rl = *(const __half2*)(Rl + (size_t)row * DMOD + col);
            float v0 = acc[n8][half * 2 + 0] + bv.x + __half2float(rh.x) + __half2float(rl.x);
            float v1 = acc[n8][half * 2 + 1] + bv.y + __half2float(rh.y) + __half2float(rl.y);
            acc[n8][half * 2 + 0] = v0;
            acc[n8][half * 2 + 1] = v1;
            if (half == 0) { s0 += v0 + v1; q0 += v0 * v0 + v1 * v1; }
            else           { s1 += v0 + v1; q1 += v0 * v0 + v1 * v1; }
        }
    }
#pragma unroll
    for (int o = 1; o < 4; o <<= 1) {
        s0 += __shfl_xor_sync(0xffffffffu, s0, o);
        q0 += __shfl_xor_sync(0xffffffffu, q0, o);
        s1 += __shfl_xor_sync(0xffffffffu, s1, o);
        q1 += __shfl_xor_sync(0xffffffffu, q1, o);
    }
    if (tig == 0) {
        int r0 = wm * 16 + gid;
        redS[r0 * 4 + wn] = s0;       redQ[r0 * 4 + wn] = q0;
        redS[(r0 + 8) * 4 + wn] = s1; redQ[(r0 + 8) * 4 + wn] = q1;
    }
    __syncthreads();

    int r0 = wm * 16 + gid;
    float ts0 = redS[r0 * 4 + 0] + redS[r0 * 4 + 1] + redS[r0 * 4 + 2] + redS[r0 * 4 + 3];
    float tq0 = redQ[r0 * 4 + 0] + redQ[r0 * 4 + 1] + redQ[r0 * 4 + 2] + redQ[r0 * 4 + 3];
    int r1 = r0 + 8;
    float ts1 = redS[r1 * 4 + 0] + redS[r1 * 4 + 1] + redS[r1 * 4 + 2] + redS[r1 * 4 + 3];
    float tq1 = redQ[r1 * 4 + 0] + redQ[r1 * 4 + 1] + redQ[r1 * 4 + 2] + redQ[r1 * 4 + 3];
    float mean0 = ts0 * (1.0f / 256.0f);
    float inv0  = rsqrtf(tq0 * (1.0f / 256.0f) - mean0 * mean0 + 1e-5f);
    float mean1 = ts1 * (1.0f / 256.0f);
    float inv1  = rsqrtf(tq1 * (1.0f / 256.0f) - mean1 * mean1 + 1e-5f);

#pragma unroll
    for (int n8 = 0; n8 < 8; n8++) {
        int col = wn * 64 + n8 * 8 + tig * 2;
        float2 gv = *(const float2*)(gamma + col);
        float2 be = *(const float2*)(beta + col);
#pragma unroll
        for (int half = 0; half < 2; half++) {
            int row = bm + wm * 16 + gid + half * 8;
            float mean = half ? mean1 : mean0;
            float inv  = half ? inv1  : inv0;
            float v0 = (acc[n8][half * 2 + 0] - mean) * inv * gv.x + be.x;
            float v1 = (acc[n8][half * 2 + 1] - mean) * inv * gv.y + be.y;
            __half h0, l0, h1, l1;
            split2h(v0, h0, l0);
            split2h(v1, h1, l1);
            *(__half2*)(Oh + (size_t)row * DMOD + col) = __halves2half2(h0, h1);
            *(__half2*)(Ol + (size_t)row * DMOD + col) = __halves2half2(l0, l1);
        }
    }
}

__global__ void kv_partial(const float* __restrict__ Kin, const float* __restrict__ Vin,
                           float* __restrict__ KVp, float* __restrict__ Ksp) {
    int blk = blockIdx.x;
    int bh = blk >> 4, ch = blk & (KVCH - 1);
    int b = bh >> 3, h = bh & 7;
    int tid = threadIdx.x;
    __shared__ float Ks[32][36];
    __shared__ float Vs[32][32];
    int m = tid >> 3, d0 = (tid & 7) * 4;
    float acc[4] = {0.f, 0.f, 0.f, 0.f};
    float ks[4]  = {0.f, 0.f, 0.f, 0.f};
    int lr = tid >> 3, lc = (tid & 7) * 4;
    int lbeg = ch * (LSEQ / KVCH), lend = lbeg + (LSEQ / KVCH);
    for (int l0 = lbeg; l0 < lend; l0 += 32) {
        size_t base = ((size_t)(b * LSEQ + l0 + lr)) * DMOD + h * HDIM + lc;
        float4 kv4 = *(const float4*)(Kin + base);
        float4 vv4 = *(const float4*)(Vin + base);
        Ks[lr][lc + 0] = kv4.x; Ks[lr][lc + 1] = kv4.y;
        Ks[lr][lc + 2] = kv4.z; Ks[lr][lc + 3] = kv4.w;
        *(float4*)&Vs[lr][lc] = vv4;
        __syncthreads();
#pragma unroll 8
        for (int r = 0; r < 32; r++) {
            float vm = Vs[r][m];
#pragma unroll
            for (int j = 0; j < 4; j++) acc[j] = fmaf(vm, Ks[r][d0 + j], acc[j]);
            if (m == 0) {
#pragma unroll
                for (int j = 0; j < 4; j++) ks[j] += Ks[r][d0 + j];
            }
        }
        __syncthreads();
    }
    size_t obase = ((size_t)blk * HDIM + m) * HDIM + d0;
#pragma unroll
    for (int j = 0; j < 4; j++) KVp[obase + j] = acc[j];
    if (m == 0) {
#pragma unroll
        for (int j = 0; j < 4; j++) Ksp[blk * HDIM + d0 + j] = ks[j];
    }
}

__global__ void kv_finalize(const float* __restrict__ KVp, const float* __restrict__ Ksp,
                            float* __restrict__ KV, float* __restrict__ Ksum) {
    int bh = blockIdx.x, tid = threadIdx.x;
#pragma unroll
    for (int o = 0; o < 4; o++) {
        int idx = tid + o * 256;
        float s = 0.f;
#pragma unroll
        for (int c = 0; c < KVCH; c++)
            s += KVp[((size_t)(bh * KVCH + c)) * (HDIM * HDIM) + idx];
        KV[(size_t)bh * (HDIM * HDIM) + idx] = s;
    }
    if (tid < HDIM) {
        float s = 0.f;
#pragma unroll
        for (int c = 0; c < KVCH; c++)
            s += Ksp[(bh * KVCH + c) * HDIM + tid];
        Ksum[bh * HDIM + tid] = s;
    }
}

__global__ void attn_apply(const float* __restrict__ Q, const float* __restrict__ KV,
                           const float* __restrict__ Ksum,
                           __half* __restrict__ Mh, __half* __restrict__ Ml) {
    int blk = blockIdx.x;
    int b = blk >> 5, lt = (blk & 31) * 128;
    int tid = threadIdx.x;
    __shared__ float KVs[NHEAD * HDIM * 33];
    __shared__ float Ksums[NHEAD * HDIM];
    for (int i = tid; i < NHEAD * HDIM * HDIM; i += 256) {
        int h = i >> 10, m = (i >> 5) & 31, d = i & 31;
        KVs[(h * HDIM + m) * 33 + d] = KV[((size_t)(b * NHEAD + h) * HDIM + m) * HDIM + d];
    }
    for (int i = tid; i < NHEAD * HDIM; i += 256)
        Ksums[i] = Ksum[b * NHEAD * HDIM + i];
    __syncthreads();
    int h = tid >> 5, m = tid & 31;
    const float* kvrow = &KVs[(h * HDIM + m) * 33];
    const float* ksr   = &Ksums[h * HDIM];
    for (int r = 0; r < 128; r++) {
        int l = lt + r;
        const float* q = Q + ((size_t)(b * LSEQ + l)) * DMOD + h * HDIM;
        float num = 0.f, den = 0.f;
#pragma unroll
        for (int d = 0; d < HDIM; d += 4) {
            float4 qv = *(const float4*)(q + d);
            num = fmaf(qv.x, kvrow[d],     num);
            num = fmaf(qv.y, kvrow[d + 1], num);
            num = fmaf(qv.z, kvrow[d + 2], num);
            num = fmaf(qv.w, kvrow[d + 3], num);
            den = fmaf(qv.x, ksr[d],     den);
            den = fmaf(qv.y, ksr[d + 1], den);
            den = fmaf(qv.z, ksr[d + 2], den);
            den = fmaf(qv.w, ksr[d + 3], den);
        }
        float o = num / (den + 1e-6f);
        __half hh, ll;
        split2h(o, hh, ll);
        size_t oi = ((size_t)(b * LSEQ + l)) * DMOD + tid;
        Mh[oi] = hh; Ml[oi] = ll;
    }
}

__global__ void write_out(const __half* __restrict__ Xh, const __half* __restrict__ Xl,
                          float* __restrict__ out) {
    __shared__ float s[32][33];
    int n  = blockIdx.y;
    int ct = blockIdx.x >> 7, lt = blockIdx.x & 127;
    int c0 = ct * 32, l0 = lt * 32;
    int tid = threadIdx.x;
#pragma unroll
    for (int p = 0; p < 4; p++) {
        int l = p * 8 + (tid >> 5), c = tid & 31;
        size_t idx = ((size_t)n * LSEQ + l0 + l) * DMOD + c0 + c;
        s[l][c] = __half2float(Xh[idx]) + __half2float(Xl[idx]);
    }
    __syncthreads();
#pragma unroll
    for (int p = 0; p < 4; p++) {
        int c = p * 8 + (tid >> 5), l = tid & 31;
        out[((size_t)n * DMOD + c0 + c) * LSEQ + l0 + l] = s[l][c];
    }
}

extern "C" void kernel_launch(void* const* d_in, const int* in_sizes, int n_in,
                              void* d_out, int out_size) {
    const float* ref = (const float*)d_in[0];
    const float* src = (const float*)d_in[1];
    const float* Wq  = (const float*)d_in[2];
    const float* bq  = (const float*)d_in[3];
    const float* Wk  = (const float*)d_in[4];
    const float* bk  = (const float*)d_in[5];
    const float* Wv  = (const float*)d_in[6];
    const float* bv  = (const float*)d_in[7];
    const float* Wo  = (const float*)d_in[8];
    const float* bo  = (const float*)d_in[9];
    const float* W1  = (const float*)d_in[10];
    const float* b1  = (const float*)d_in[11];
    const float* W2  = (const float*)d_in[12];
    const float* b2  = (const float*)d_in[13];
    const float* G1  = (const float*)d_in[14];
    const float* Be1 = (const float*)d_in[15];
    const float* G2  = (const float*)d_in[16];
    const float* Be2 = (const float*)d_in[17];

    float *q, *k, *v, *kv, *ks, *kvp, *ksp;
    __half *xh, *xl, *p2h, *p2l, *mh, *ml, *hh, *hl, *wth;
    cudaGetSymbolAddress((void**)&q,   g_q);
    cudaGetSymbolAddress((void**)&k,   g_k);
    cudaGetSymbolAddress((void**)&v,   g_v);
    cudaGetSymbolAddress((void**)&kv,  g_kv);
    cudaGetSymbolAddress((void**)&ks,  g_ks);
    cudaGetSymbolAddress((void**)&kvp, g_kvp);
    cudaGetSymbolAddress((void**)&ksp, g_ksp);
    cudaGetSymbolAddress((void**)&xh,  g_xh);
    cudaGetSymbolAddress((void**)&xl,  g_xl);
    cudaGetSymbolAddress((void**)&p2h, g_p2h);
    cudaGetSymbolAddress((void**)&p2l, g_p2l);
    cudaGetSymbolAddress((void**)&mh,  g_mh);
    cudaGetSymbolAddress((void**)&ml,  g_ml);
    cudaGetSymbolAddress((void**)&hh,  g_hh);
    cudaGetSymbolAddress((void**)&hl,  g_hl);
    cudaGetSymbolAddress((void**)&wth, g_wth);

    cudaFuncSetAttribute(gemm_w,  cudaFuncAttributeMaxDynamicSharedMemorySize, GSMEM_W);
    cudaFuncSetAttribute(gemm_ln, cudaFuncAttributeMaxDynamicSharedMemorySize, GSMEM_LN);

    wconv_all<<<2048, 256>>>(Wq, Wk, Wv, Wo, W1, W2);
    {
        dim3 pb(8 * 128, 8);
        posenc_kernel<<<pb, 256>>>(ref, src, xh, xl, p2h, p2l);
    }

    dim3 gw256(MROWS / 128, 1);   // N=256
    dim3 gw512(MROWS / 128, 2);   // N=512

    for (int li = 0; li < 4; li++) {
        size_t wl  = (size_t)li * WLAYER;
        size_t bo_ = (size_t)li * DMOD;
        size_t b1o = (size_t)li * DFF;
        const __half* sh = (li % 2 == 0) ? xh : p2h;
        const __half* sl = (li % 2 == 0) ? xl : p2l;

        gemm_w<<<gw256, 1024, GSMEM_W>>>(xh, xl, wth + wl + 0,      bq + bo_, q, 0, 0, DMOD, DMOD, 1);
        gemm_w<<<gw256, 1024, GSMEM_W>>>(sh, sl, wth + wl + 65536,  bk + bo_, k, 0, 0, DMOD, DMOD, 1);
        gemm_w<<<gw256, 1024, GSMEM_W>>>(sh, sl, wth + wl + 131072, bv + bo_, v, 0, 0, DMOD, DMOD, 0);

        kv_partial<<<BATCH * NHEAD * KVCH, 256>>>(k, v, kvp, ksp);
        kv_finalize<<<BATCH * NHEAD, 256>>>(kvp, ksp, kv, ks);
        attn_apply<<<BATCH * 32, 256>>>(q, kv, ks, mh, ml);

        gemm_ln<<<MROWS / 128, 1024, GSMEM_LN>>>(mh, ml, wth + wl + 196608, bo + bo_,
                                                 xh, xl, G1 + bo_, Be1 + bo_, xh, xl, DMOD);

        gemm_w<<<gw512, 1024, GSMEM_W>>>(xh, xl, wth + wl + 262144, b1 + b1o, 0, hh, hl, DFF, DMOD, 2);

        gemm_ln<<<MROWS / 128, 1024, GSMEM_LN>>>(hh, hl, wth + wl + 393216, b2 + bo_,
                                                 xh, xl, G2 + bo_, Be2 + bo_, xh, xl, DFF);
    }

    {
        dim3 wb(8 * 128, 8);
        write_out<<<wb, 256>>>(xh, xl, (float*)d_out);
    }
}

// round 16
// speedup vs baseline: 1.1079x; 1.1079x over previous
#include <cuda_runtime.h>
#include <cuda_fp16.h>
#include <math.h>
#include <stdint.h>

#define BATCH 8
#define LSEQ  4096
#define DMOD  256
#define DFF   512
#define NHEAD 8
#define HDIM  32
#define MROWS (BATCH * LSEQ)
#define KVCH  16
#define STG   49152            /* gemm_hp stage: Ah 16K | Al 16K | Bh 16K */
#define GSMEM (2 * STG)
#define STG2  65536            /* gemm_ln stage: Ah 16K | Al 16K | B 32K */
#define GSMEM_LN (3 * STG2 + 4096)
#define WLAYER 524288

__device__ float g_q  [MROWS * DMOD];
__device__ float g_kvb[MROWS * DFF];     // combined K|V projections [M,512]
__device__ float g_kv [BATCH * NHEAD * HDIM * HDIM];
__device__ float g_ks [BATCH * NHEAD * HDIM];
__device__ float g_kvp[BATCH * NHEAD * KVCH * HDIM * HDIM];
__device__ float g_ksp[BATCH * NHEAD * KVCH * HDIM];
__device__ float g_bkv[4 * DFF];
__device__ __half g_xh [MROWS * DMOD];
__device__ __half g_xl [MROWS * DMOD];
__device__ __half g_p2h[MROWS * DMOD];
__device__ __half g_p2l[MROWS * DMOD];
__device__ __half g_mh [MROWS * DMOD];
__device__ __half g_ml [MROWS * DMOD];
__device__ __half g_hh [MROWS * DFF];
__device__ __half g_hl [MROWS * DFF];
__device__ __half g_wth[4 * WLAYER];

__device__ __forceinline__ uint32_t smem_u32(const void* p) {
    uint32_t a;
    asm("{ .reg .u64 t; cvta.to.shared.u64 t, %1; cvt.u32.u64 %0, t; }" : "=r"(a) : "l"(p));
    return a;
}
__device__ __forceinline__ uint32_t swz128(uint32_t off) { return off ^ ((off >> 3) & 0x70); }
__device__ __forceinline__ void cpa16(uint32_t dst, const void* src) {
    asm volatile("cp.async.cg.shared.global [%0], [%1], 16;" :: "r"(dst), "l"(src));
}
__device__ __forceinline__ void ldsm4(uint32_t* r, uint32_t a) {
    asm volatile("ldmatrix.sync.aligned.m8n8.x4.shared.b16 {%0,%1,%2,%3}, [%4];"
                 : "=r"(r[0]), "=r"(r[1]), "=r"(r[2]), "=r"(r[3]) : "r"(a));
}
__device__ __forceinline__ void mma16816(float* c, const uint32_t* a, uint32_t b0, uint32_t b1) {
    asm volatile(
        "mma.sync.aligned.m16n8k16.row.col.f32.f16.f16.f32 "
        "{%0,%1,%2,%3},{%4,%5,%6,%7},{%8,%9},{%0,%1,%2,%3};"
        : "+f"(c[0]), "+f"(c[1]), "+f"(c[2]), "+f"(c[3])
        : "r"(a[0]), "r"(a[1]), "r"(a[2]), "r"(a[3]), "r"(b0), "r"(b1));
}
__device__ __forceinline__ void split2h(float x, __half& h, __half& l) {
    h = __float2half_rn(x);
    l = __float2half_rn(x - __half2float(h));
}

__global__ void posenc_kernel(const float* __restrict__ ref, const float* __restrict__ src,
                              __half* __restrict__ p1h, __half* __restrict__ p1l,
                              __half* __restrict__ p2h, __half* __restrict__ p2l) {
    __shared__ float s[32][33];
    int img = blockIdx.y >> 2, n = blockIdx.y & 3;
    int ct = blockIdx.x >> 7, lt = blockIdx.x & 127;
    int c0 = ct * 32, l0 = lt * 32;
    int tid = threadIdx.x;
    const float* inp = (img == 0) ? ref : src;
#pragma unroll
    for (int p = 0; p < 4; p++) {
        int c = p * 8 + (tid >> 5), l = tid & 31;
        s[c][l] = inp[((size_t)n * DMOD + c0 + c) * LSEQ + l0 + l];
    }
    __syncthreads();
#pragma unroll
    for (int p = 0; p < 4; p++) {
        int l = p * 8 + (tid >> 5), c = tid & 31;
        int cg = c0 + c, lg = l0 + l;
        int ii = cg >> 2, jj = cg & 3;
        float dv = __expf(-(float)ii * (logf(10000.0f) / 64.0f));
        int w = lg & 63, hh = lg >> 6;
        float arg = (jj < 2 ? (float)w : (float)hh) * dv;
        float pe = (jj & 1) ? cosf(arg) : sinf(arg);
        float val = s[c][l] + pe;
        size_t o1 = ((size_t)(img * 4 + n) * LSEQ + lg) * DMOD + cg;
        size_t o2 = ((size_t)((1 - img) * 4 + n) * LSEQ + lg) * DMOD + cg;
        __half h, lo;
        split2h(val, h, lo);
        p1h[o1] = h; p1l[o1] = lo;
        p2h[o2] = h; p2l[o2] = lo;
    }
}

__global__ void wconv_all(const float* __restrict__ Wq, const float* __restrict__ Wk,
                          const float* __restrict__ Wv, const float* __restrict__ Wo,
                          const float* __restrict__ W1, const float* __restrict__ W2,
                          const float* __restrict__ bk, const float* __restrict__ bv) {
    __shared__ float s[32][33];
    int li = blockIdx.x >> 9;
    int r  = blockIdx.x & 511;
    if (blockIdx.x < 4 && threadIdx.x < 256) {
        // also build concatenated kv bias (redundant across the 4 blocks' threads OK)
        g_bkv[blockIdx.x * DFF + threadIdx.x]       = bk[blockIdx.x * DMOD + threadIdx.x];
        g_bkv[blockIdx.x * DFF + 256 + threadIdx.x] = bv[blockIdx.x * DMOD + threadIdx.x];
    }
    const float* src;
    size_t dsto;
    int K, N, n0, k0;
    if (r < 256) {
        int mat = r >> 6, t = r & 63;
        K = 256; N = 256;
        n0 = (t & 7) * 32; k0 = (t >> 3) * 32;
        const float* bases[4] = {Wq, Wk, Wv, Wo};
        src  = bases[mat] + (size_t)li * 65536;
        dsto = (size_t)li * WLAYER + (size_t)mat * 65536;
    } else if (r < 384) {
        int t = r - 256;
        K = 256; N = 512;
        n0 = (t & 15) * 32; k0 = (t >> 4) * 32;
        src  = W1 + (size_t)li * 131072;
        dsto = (size_t)li * WLAYER + 262144;
    } else {
        int t = r - 384;
        K = 512; N = 256;
        n0 = (t & 7) * 32; k0 = (t >> 3) * 32;
        src  = W2 + (size_t)li * 131072;
        dsto = (size_t)li * WLAYER + 393216;
    }
    int tid = threadIdx.x;
#pragma unroll
    for (int p = 0; p < 4; p++) {
        int kk = p * 8 + (tid >> 5), nn = tid & 31;
        s[kk][nn] = src[(size_t)(k0 + kk) * N + n0 + nn];
    }
    __syncthreads();
#pragma unroll
    for (int p = 0; p < 4; p++) {
        int nn = p * 8 + (tid >> 5), kk = tid & 31;
        g_wth[dsto + (size_t)(n0 + nn) * K + k0 + kk] = __float2half_rn(s[kk][nn]);
    }
}

// ---------------- gemm_hp: 128x128 tile, 256 threads, 2 CTAs/SM ----------------
__device__ __forceinline__ void load_stage(const __half* Ah, const __half* Al,
                                           const __half* Bh,
                                           int bm, int bn, int K, int k0,
                                           uint32_t sb, int tid) {
#pragma unroll
    for (int it = 0; it < 4; it++) {
        int c = tid + it * 256;
        int r = c >> 3, seg = c & 7;
        uint32_t d = swz128((uint32_t)(r * 128 + seg * 16));
        size_t ga = (size_t)(bm + r) * K + k0 + seg * 8;
        size_t gb = (size_t)(bn + r) * K + k0 + seg * 8;
        cpa16(sb + d,         Ah + ga);
        cpa16(sb + 16384 + d, Al + ga);
        cpa16(sb + 32768 + d, Bh + gb);
    }
    asm volatile("cp.async.commit_group;" ::: "memory");
}

__global__ __launch_bounds__(256, 2)
void gemm_hp(const __half* __restrict__ Ah, const __half* __restrict__ Al,
             const __half* __restrict__ Bh,
             const float* __restrict__ bias,
             float* __restrict__ Cf, __half* __restrict__ Ch, __half* __restrict__ Cl,
             int M, int N, int K, int mode) {
    extern __shared__ char smem[];
    uint32_t sb = smem_u32(smem);
    int tid = threadIdx.x, lane = tid & 31, warp = tid >> 5;
    int wm = warp >> 1, wn = warp & 1;
    int bm = blockIdx.y * 128, bn = blockIdx.x * 128;

    float acc[2][8][4];
#pragma unroll
    for (int i = 0; i < 2; i++)
#pragma unroll
        for (int j = 0; j < 8; j++)
#pragma unroll
            for (int r = 0; r < 4; r++) acc[i][j][r] = 0.0f;

    const int KT = K >> 6;
    load_stage(Ah, Al, Bh, bm, bn, K, 0, sb, tid);

    int lrow = (lane & 7) + ((lane >> 3) & 1) * 8;
    int kseg = (lane >> 4) * 16;

    for (int kt = 0; kt < KT; kt++) {
        asm volatile("cp.async.wait_group 0;" ::: "memory");
        __syncthreads();
        if (kt + 1 < KT)
            load_stage(Ah, Al, Bh, bm, bn, K, (kt + 1) << 6, sb + ((kt + 1) & 1) * STG, tid);

        uint32_t offA = sb + (kt & 1) * STG;
        uint32_t offAl = offA + 16384, offB = offA + 32768;
#pragma unroll
        for (int kk = 0; kk < 4; kk++) {
            int kb = kk * 32 + kseg;
            uint32_t ah[2][4], al[2][4], bfr[4][4];
#pragma unroll
            for (int mt = 0; mt < 2; mt++) {
                uint32_t off = swz128((uint32_t)((wm * 32 + mt * 16 + lrow) * 128 + kb));
                ldsm4(ah[mt], offA  + off);
                ldsm4(al[mt], offAl + off);
            }
#pragma unroll
            for (int j = 0; j < 4; j++) {
                uint32_t off = swz128((uint32_t)((wn * 64 + j * 16 + lrow) * 128 + kb));
                ldsm4(bfr[j], offB + off);
            }
#pragma unroll
            for (int mt = 0; mt < 2; mt++)
#pragma unroll
                for (int j = 0; j < 4; j++)
#pragma unroll
                    for (int s = 0; s < 2; s++) {
                        int n8 = j * 2 + s;
                        mma16816(acc[mt][n8], ah[mt], bfr[j][s], bfr[j][2 + s]);
                        mma16816(acc[mt][n8], al[mt], bfr[j][s], bfr[j][2 + s]);
                    }
        }
    }
    __syncthreads();

    int gid = lane >> 2, tig = lane & 3;
#pragma unroll
    for (int n8 = 0; n8 < 8; n8++) {
        int col = bn + wn * 64 + n8 * 8 + tig * 2;
        float2 bv = *(const float2*)(bias + col);
        bool elu = (mode == 1) || (mode == 3 && col < 256);
#pragma unroll
        for (int mt = 0; mt < 2; mt++) {
            int row0 = bm + wm * 32 + mt * 16 + gid;
#pragma unroll
            for (int half = 0; half < 2; half++) {
                int row = row0 + half * 8;
                float v0 = acc[mt][n8][half * 2 + 0] + bv.x;
                float v1 = acc[mt][n8][half * 2 + 1] + bv.y;
                if (elu) {
                    v0 = (v0 > 0.f) ? v0 + 1.f : __expf(v0);
                    v1 = (v1 > 0.f) ? v1 + 1.f : __expf(v1);
                } else if (mode == 2) {
                    v0 = fmaxf(v0, 0.f);
                    v1 = fmaxf(v1, 0.f);
                }
                if (mode == 2) {
                    __half h0, l0, h1, l1;
                    split2h(v0, h0, l0);
                    split2h(v1, h1, l1);
                    *(__half2*)(Ch + (size_t)row * N + col) = __halves2half2(h0, h1);
                    *(__half2*)(Cl + (size_t)row * N + col) = __halves2half2(l0, l1);
                } else {
                    *(float2*)(Cf + (size_t)row * N + col) = make_float2(v0, v1);
                }
            }
        }
    }
}

// ---------------- gemm_ln: 128x256 tile, fused bias+residual+LayerNorm ---------
__device__ __forceinline__ void load_stage_ln(const __half* Ah, const __half* Al,
                                              const __half* Bh,
                                              int bm, int K, int k0,
                                              uint32_t sb, int tid) {
    {
        int r = tid >> 3, seg = tid & 7;
        uint32_t d = swz128((uint32_t)(r * 128 + seg * 16));
        size_t ga = (size_t)(bm + r) * K + k0 + seg * 8;
        cpa16(sb + d,         Ah + ga);
        cpa16(sb + 16384 + d, Al + ga);
    }
#pragma unroll
    for (int it = 0; it < 2; it++) {
        int c = tid + it * 1024;
        int r = c >> 3, seg = c & 7;
        uint32_t d = swz128((uint32_t)(r * 128 + seg * 16));
        cpa16(sb + 32768 + d, Bh + (size_t)r * K + k0 + seg * 8);
    }
    asm volatile("cp.async.commit_group;" ::: "memory");
}

__global__ __launch_bounds__(1024, 1)
void gemm_ln(const __half* __restrict__ Ah, const __half* __restrict__ Al,
             const __half* __restrict__ Bh,
             const float* __restrict__ bias,
             const __half* __restrict__ Rh, const __half* __restrict__ Rl,
             const float* __restrict__ gamma, const float* __restrict__ beta,
             __half* __restrict__ Oh, __half* __restrict__ Ol,
             int K) {
    extern __shared__ char smem[];
    uint32_t sb = smem_u32(smem);
    float* redS = (float*)(smem + 3 * STG2);
    float* redQ = (float*)(smem + 3 * STG2 + 2048);
    int tid = threadIdx.x, lane = tid & 31, warp = tid >> 5;
    int wm = warp >> 2, wn = warp & 3;
    int bm = blockIdx.x * 128;

    float acc[8][4];
#pragma unroll
    for (int j = 0; j < 8; j++)
#pragma unroll
        for (int r = 0; r < 4; r++) acc[j][r] = 0.0f;

    const int KT = K >> 6;
    load_stage_ln(Ah, Al, Bh, bm, K, 0, sb, tid);
    if (KT > 1) load_stage_ln(Ah, Al, Bh, bm, K, 64, sb + STG2, tid);

    int lrow = (lane & 7) + ((lane >> 3) & 1) * 8;
    int kseg = (lane >> 4) * 16;

    for (int kt = 0; kt < KT; kt++) {
        if (kt + 1 < KT) asm volatile("cp.async.wait_group 1;" ::: "memory");
        else             asm volatile("cp.async.wait_group 0;" ::: "memory");
        __syncthreads();
        if (kt + 2 < KT)
            load_stage_ln(Ah, Al, Bh, bm, K, (kt + 2) << 6, sb + ((kt + 2) % 3) * STG2, tid);

        uint32_t offA = sb + (kt % 3) * STG2;
        uint32_t offAl = offA + 16384, offB = offA + 32768;
#pragma unroll
        for (int kk = 0; kk < 4; kk++) {
            int kb = kk * 32 + kseg;
            uint32_t ah[4], al[4];
            {
                uint32_t off = swz128((uint32_t)((wm * 16 + lrow) * 128 + kb));
                ldsm4(ah, offA  + off);
                ldsm4(al, offAl + off);
            }
#pragma unroll
            for (int j = 0; j < 4; j++) {
                uint32_t bfr[4];
                uint32_t off = swz128((uint32_t)((wn * 64 + j * 16 + lrow) * 128 + kb));
                ldsm4(bfr, offB + off);
#pragma unroll
                for (int s = 0; s < 2; s++) {
                    int n8 = j * 2 + s;
                    mma16816(acc[n8], ah, bfr[s], bfr[2 + s]);
                    mma16816(acc[n8], al, bfr[s], bfr[2 + s]);
                }
            }
        }
    }
    __syncthreads();

    int gid = lane >> 2, tig = lane & 3;
    float s0 = 0.f, q0 = 0.f, s1 = 0.f, q1 = 0.f;
#pragma unroll
    for (int n8 = 0; n8 < 8; n8++) {
        int col = wn * 64 + n8 * 8 + tig * 2;
        float2 bv = *(const float2*)(bias + col);
#pragma unroll
        for (int half = 0; half < 2; half++) {
            int row = bm + wm * 16 + gid + half * 8;
            __half2 rh = *(const __half2*)(Rh + (size_t)row * DMOD + col);
            __half2 rl = *(const __half2*)(Rl + (size_t)row * DMOD + col);
            float v0 = acc[n8][half * 2 + 0] + bv.x + __half2float(rh.x) + __half2float(rl.x);
            float v1 = acc[n8][half * 2 + 1] + bv.y + __half2float(rh.y) + __half2float(rl.y);
            acc[n8][half * 2 + 0] = v0;
            acc[n8][half * 2 + 1] = v1;
            if (half == 0) { s0 += v0 + v1; q0 += v0 * v0 + v1 * v1; }
            else           { s1 += v0 + v1; q1 += v0 * v0 + v1 * v1; }
        }
    }
#pragma unroll
    for (int o = 1; o < 4; o <<= 1) {
        s0 += __shfl_xor_sync(0xffffffffu, s0, o);
        q0 += __shfl_xor_sync(0xffffffffu, q0, o);
        s1 += __shfl_xor_sync(0xffffffffu, s1, o);
        q1 += __shfl_xor_sync(0xffffffffu, q1, o);
    }
    if (tig == 0) {
        int r0 = wm * 16 + gid;
        redS[r0 * 4 + wn] = s0;       redQ[r0 * 4 + wn] = q0;
        redS[(r0 + 8) * 4 + wn] = s1; redQ[(r0 + 8) * 4 + wn] = q1;
    }
    __syncthreads();

    int r0 = wm * 16 + gid;
    float ts0 = redS[r0 * 4 + 0] + redS[r0 * 4 + 1] + redS[r0 * 4 + 2] + redS[r0 * 4 + 3];
    float tq0 = redQ[r0 * 4 + 0] + redQ[r0 * 4 + 1] + redQ[r0 * 4 + 2] + redQ[r0 * 4 + 3];
    int r1 = r0 + 8;
    float ts1 = redS[r1 * 4 + 0] + redS[r1 * 4 + 1] + redS[r1 * 4 + 2] + redS[r1 * 4 + 3];
    float tq1 = redQ[r1 * 4 + 0] + redQ[r1 * 4 + 1] + redQ[r1 * 4 + 2] + redQ[r1 * 4 + 3];
    float mean0 = ts0 * (1.0f / 256.0f);
    float inv0  = rsqrtf(tq0 * (1.0f / 256.0f) - mean0 * mean0 + 1e-5f);
    float mean1 = ts1 * (1.0f / 256.0f);
    float inv1  = rsqrtf(tq1 * (1.0f / 256.0f) - mean1 * mean1 + 1e-5f);

#pragma unroll
    for (int n8 = 0; n8 < 8; n8++) {
        int col = wn * 64 + n8 * 8 + tig * 2;
        float2 gv = *(const float2*)(gamma + col);
        float2 be = *(const float2*)(beta + col);
#pragma unroll
        for (int half = 0; half < 2; half++) {
            int row = bm + wm * 16 + gid + half * 8;
            float mean = half ? mean1 : mean0;
            float inv  = half ? inv1  : inv0;
            float v0 = (acc[n8][half * 2 + 0] - mean) * inv * gv.x + be.x;
            float v1 = (acc[n8][half * 2 + 1] - mean) * inv * gv.y + be.y;
            __half h0, l0, h1, l1;
            split2h(v0, h0, l0);
            split2h(v1, h1, l1);
            *(__half2*)(Oh + (size_t)row * DMOD + col) = __halves2half2(h0, h1);
            *(__half2*)(Ol + (size_t)row * DMOD + col) = __halves2half2(l0, l1);
        }
    }
}

// ---------------- KV partial over combined [M,512] buffer ----------------------
__global__ void kv_partial(const float* __restrict__ KVin,
                           float* __restrict__ KVp, float* __restrict__ Ksp) {
    int blk = blockIdx.x;
    int bh = blk >> 4, ch = blk & (KVCH - 1);
    int b = bh >> 3, h = bh & 7;
    int tid = threadIdx.x;
    __shared__ float Ks[32][36];
    __shared__ float Vs[32][32];
    int m = tid >> 3, d0 = (tid & 7) * 4;
    float acc[4] = {0.f, 0.f, 0.f, 0.f};
    float ks[4]  = {0.f, 0.f, 0.f, 0.f};
    int lr = tid >> 3, lc = (tid & 7) * 4;
    int lbeg = ch * (LSEQ / KVCH), lend = lbeg + (LSEQ / KVCH);
    for (int l0 = lbeg; l0 < lend; l0 += 32) {
        size_t base = ((size_t)(b * LSEQ + l0 + lr)) * DFF + h * HDIM + lc;
        float4 kv4 = *(const float4*)(KVin + base);
        float4 vv4 = *(const float4*)(KVin + base + 256);
        Ks[lr][lc + 0] = kv4.x; Ks[lr][lc + 1] = kv4.y;
        Ks[lr][lc + 2] = kv4.z; Ks[lr][lc + 3] = kv4.w;
        *(float4*)&Vs[lr][lc] = vv4;
        __syncthreads();
#pragma unroll 8
        for (int r = 0; r < 32; r++) {
            float vm = Vs[r][m];
#pragma unroll
            for (int j = 0; j < 4; j++) acc[j] = fmaf(vm, Ks[r][d0 + j], acc[j]);
            if (m == 0) {
#pragma unroll
                for (int j = 0; j < 4; j++) ks[j] += Ks[r][d0 + j];
            }
        }
        __syncthreads();
    }
    size_t obase = ((size_t)blk * HDIM + m) * HDIM + d0;
#pragma unroll
    for (int j = 0; j < 4; j++) KVp[obase + j] = acc[j];
    if (m == 0) {
#pragma unroll
        for (int j = 0; j < 4; j++) Ksp[blk * HDIM + d0 + j] = ks[j];
    }
}

__global__ void kv_finalize(const float* __restrict__ KVp, const float* __restrict__ Ksp,
                            float* __restrict__ KV, float* __restrict__ Ksum) {
    int bh = blockIdx.x, tid = threadIdx.x;
#pragma unroll
    for (int o = 0; o < 4; o++) {
        int idx = tid + o * 256;
        float s = 0.f;
#pragma unroll
        for (int c = 0; c < KVCH; c++)
            s += KVp[((size_t)(bh * KVCH + c)) * (HDIM * HDIM) + idx];
        KV[(size_t)bh * (HDIM * HDIM) + idx] = s;
    }
    if (tid < HDIM) {
        float s = 0.f;
#pragma unroll
        for (int c = 0; c < KVCH; c++)
            s += Ksp[(bh * KVCH + c) * HDIM + tid];
        Ksum[bh * HDIM + tid] = s;
    }
}

__global__ void attn_apply(const float* __restrict__ Q, const float* __restrict__ KV,
                           const float* __restrict__ Ksum,
                           __half* __restrict__ Mh, __half* __restrict__ Ml) {
    int blk = blockIdx.x;
    int b = blk >> 5, lt = (blk & 31) * 128;
    int tid = threadIdx.x;
    __shared__ float KVs[NHEAD * HDIM * 33];
    __shared__ float Ksums[NHEAD * HDIM];
    for (int i = tid; i < NHEAD * HDIM * HDIM; i += 256) {
        int h = i >> 10, m = (i >> 5) & 31, d = i & 31;
        KVs[(h * HDIM + m) * 33 + d] = KV[((size_t)(b * NHEAD + h) * HDIM + m) * HDIM + d];
    }
    for (int i = tid; i < NHEAD * HDIM; i += 256)
        Ksums[i] = Ksum[b * NHEAD * HDIM + i];
    __syncthreads();
    int h = tid >> 5, m = tid & 31;
    const float* kvrow = &KVs[(h * HDIM + m) * 33];
    const float* ksr   = &Ksums[h * HDIM];
    for (int r = 0; r < 128; r++) {
        int l = lt + r;
        const float* q = Q + ((size_t)(b * LSEQ + l)) * DMOD + h * HDIM;
        float num = 0.f, den = 0.f;
#pragma unroll
        for (int d = 0; d < HDIM; d += 4) {
            float4 qv = *(const float4*)(q + d);
            num = fmaf(qv.x, kvrow[d],     num);
            num = fmaf(qv.y, kvrow[d + 1], num);
            num = fmaf(qv.z, kvrow[d + 2], num);
            num = fmaf(qv.w, kvrow[d + 3], num);
            den = fmaf(qv.x, ksr[d],     den);
            den = fmaf(qv.y, ksr[d + 1], den);
            den = fmaf(qv.z, ksr[d + 2], den);
            den = fmaf(qv.w, ksr[d + 3], den);
        }
        float o = num / (den + 1e-6f);
        __half hh, ll;
        split2h(o, hh, ll);
        size_t oi = ((size_t)(b * LSEQ + l)) * DMOD + tid;
        Mh[oi] = hh; Ml[oi] = ll;
    }
}

__global__ void write_out(const __half* __restrict__ Xh, const __half* __restrict__ Xl,
                          float* __restrict__ out) {
    __shared__ float s[32][33];
    int n  = blockIdx.y;
    int ct = blockIdx.x >> 7, lt = blockIdx.x & 127;
    int c0 = ct * 32, l0 = lt * 32;
    int tid = threadIdx.x;
#pragma unroll
    for (int p = 0; p < 4; p++) {
        int l = p * 8 + (tid >> 5), c = tid & 31;
        size_t idx = ((size_t)n * LSEQ + l0 + l) * DMOD + c0 + c;
        s[l][c] = __half2float(Xh[idx]) + __half2float(Xl[idx]);
    }
    __syncthreads();
#pragma unroll
    for (int p = 0; p < 4; p++) {
        int c = p * 8 + (tid >> 5), l = tid & 31;
        out[((size_t)n * DMOD + c0 + c) * LSEQ + l0 + l] = s[l][c];
    }
}

extern "C" void kernel_launch(void* const* d_in, const int* in_sizes, int n_in,
                              void* d_out, int out_size) {
    const float* ref = (const float*)d_in[0];
    const float* src = (const float*)d_in[1];
    const float* Wq  = (const float*)d_in[2];
    const float* bq  = (const float*)d_in[3];
    const float* Wk  = (const float*)d_in[4];
    const float* bk  = (const float*)d_in[5];
    const float* Wv  = (const float*)d_in[6];
    const float* bv  = (const float*)d_in[7];
    const float* Wo  = (const float*)d_in[8];
    const float* bo  = (const float*)d_in[9];
    const float* W1  = (const float*)d_in[10];
    const float* b1  = (const float*)d_in[11];
    const float* W2  = (const float*)d_in[12];
    const float* b2  = (const float*)d_in[13];
    const float* G1  = (const float*)d_in[14];
    const float* Be1 = (const float*)d_in[15];
    const float* G2  = (const float*)d_in[16];
    const float* Be2 = (const float*)d_in[17];

    float *q, *kvb, *kv, *ks, *kvp, *ksp, *bkv;
    __half *xh, *xl, *p2h, *p2l, *mh, *ml, *hh, *hl, *wth;
    cudaGetSymbolAddress((void**)&q,   g_q);
    cudaGetSymbolAddress((void**)&kvb, g_kvb);
    cudaGetSymbolAddress((void**)&kv,  g_kv);
    cudaGetSymbolAddress((void**)&ks,  g_ks);
    cudaGetSymbolAddress((void**)&kvp, g_kvp);
    cudaGetSymbolAddress((void**)&ksp, g_ksp);
    cudaGetSymbolAddress((void**)&bkv, g_bkv);
    cudaGetSymbolAddress((void**)&xh,  g_xh);
    cudaGetSymbolAddress((void**)&xl,  g_xl);
    cudaGetSymbolAddress((void**)&p2h, g_p2h);
    cudaGetSymbolAddress((void**)&p2l, g_p2l);
    cudaGetSymbolAddress((void**)&mh,  g_mh);
    cudaGetSymbolAddress((void**)&ml,  g_ml);
    cudaGetSymbolAddress((void**)&hh,  g_hh);
    cudaGetSymbolAddress((void**)&hl,  g_hl);
    cudaGetSymbolAddress((void**)&wth, g_wth);

    cudaFuncSetAttribute(gemm_hp, cudaFuncAttributeMaxDynamicSharedMemorySize, GSMEM);
    cudaFuncSetAttribute(gemm_ln, cudaFuncAttributeMaxDynamicSharedMemorySize, GSMEM_LN);

    wconv_all<<<2048, 256>>>(Wq, Wk, Wv, Wo, W1, W2, bk, bv);
    {
        dim3 pb(8 * 128, 8);
        posenc_kernel<<<pb, 256>>>(ref, src, xh, xl, p2h, p2l);
    }

    dim3 g256(2, MROWS / 128);
    dim3 g512(4, MROWS / 128);

    for (int li = 0; li < 4; li++) {
        size_t wl  = (size_t)li * WLAYER;
        size_t bo_ = (size_t)li * DMOD;
        size_t b1o = (size_t)li * DFF;
        const __half* sh = (li % 2 == 0) ? xh : p2h;
        const __half* sl = (li % 2 == 0) ? xl : p2l;

        gemm_hp<<<g256, 256, GSMEM>>>(xh, xl, wth + wl + 0, bq + bo_, q, 0, 0, MROWS, DMOD, DMOD, 1);
        // combined K|V projection (weights k@65536 and v@131072 are contiguous [512,256])
        gemm_hp<<<g512, 256, GSMEM>>>(sh, sl, wth + wl + 65536, bkv + (size_t)li * DFF,
                                      kvb, 0, 0, MROWS, DFF, DMOD, 3);

        kv_partial<<<BATCH * NHEAD * KVCH, 256>>>(kvb, kvp, ksp);
        kv_finalize<<<BATCH * NHEAD, 256>>>(kvp, ksp, kv, ks);
        attn_apply<<<BATCH * 32, 256>>>(q, kv, ks, mh, ml);

        gemm_ln<<<MROWS / 128, 1024, GSMEM_LN>>>(mh, ml, wth + wl + 196608, bo + bo_,
                                                 xh, xl, G1 + bo_, Be1 + bo_, xh, xl, DMOD);

        gemm_hp<<<g512, 256, GSMEM>>>(xh, xl, wth + wl + 262144, b1 + b1o, 0, hh, hl, MROWS, DFF, DMOD, 2);

        gemm_ln<<<MROWS / 128, 1024, GSMEM_LN>>>(hh, hl, wth + wl + 393216, b2 + bo_,
                                                 xh, xl, G2 + bo_, Be2 + bo_, xh, xl, DFF);
    }

    {
        dim3 wb(8 * 128, 8);
        write_out<<<wb, 256>>>(xh, xl, (float*)d_out);
    }
}

// round 17
// speedup vs baseline: 1.1138x; 1.0053x over previous
#include <cuda_runtime.h>
#include <cuda_fp16.h>
#include <math.h>
#include <stdint.h>

#define BATCH 8
#define LSEQ  4096
#define DMOD  256
#define DFF   512
#define NHEAD 8
#define HDIM  32
#define MROWS (BATCH * LSEQ)
#define KVCH  16
#define QKVN  768
#define STG   49152            /* gemm_hp stage: Ah 16K | Al 16K | Bh 16K */
#define GSMEM (2 * STG)
#define STG2  65536            /* gemm_ln stage: Ah 16K | Al 16K | B 32K */
#define GSMEM_LN (3 * STG2 + 4096)
#define WLAYER 524288

__device__ float g_qkv[MROWS * QKVN];    // combined Q|K|V projections [M,768]
__device__ float g_kv [BATCH * NHEAD * HDIM * HDIM];
__device__ float g_ks [BATCH * NHEAD * HDIM];
__device__ float g_kvp[BATCH * NHEAD * KVCH * HDIM * HDIM];
__device__ float g_ksp[BATCH * NHEAD * KVCH * HDIM];
__device__ float g_bqkv[4 * QKVN];
__device__ __half g_xh [MROWS * DMOD];
__device__ __half g_xl [MROWS * DMOD];
__device__ __half g_p2h[MROWS * DMOD];
__device__ __half g_p2l[MROWS * DMOD];
__device__ __half g_mh [MROWS * DMOD];
__device__ __half g_ml [MROWS * DMOD];
__device__ __half g_hh [MROWS * DFF];
__device__ __half g_hl [MROWS * DFF];
__device__ __half g_wth[4 * WLAYER];

__device__ __forceinline__ uint32_t smem_u32(const void* p) {
    uint32_t a;
    asm("{ .reg .u64 t; cvta.to.shared.u64 t, %1; cvt.u32.u64 %0, t; }" : "=r"(a) : "l"(p));
    return a;
}
__device__ __forceinline__ uint32_t swz128(uint32_t off) { return off ^ ((off >> 3) & 0x70); }
__device__ __forceinline__ void cpa16(uint32_t dst, const void* src) {
    asm volatile("cp.async.cg.shared.global [%0], [%1], 16;" :: "r"(dst), "l"(src));
}
__device__ __forceinline__ void ldsm4(uint32_t* r, uint32_t a) {
    asm volatile("ldmatrix.sync.aligned.m8n8.x4.shared.b16 {%0,%1,%2,%3}, [%4];"
                 : "=r"(r[0]), "=r"(r[1]), "=r"(r[2]), "=r"(r[3]) : "r"(a));
}
__device__ __forceinline__ void mma16816(float* c, const uint32_t* a, uint32_t b0, uint32_t b1) {
    asm volatile(
        "mma.sync.aligned.m16n8k16.row.col.f32.f16.f16.f32 "
        "{%0,%1,%2,%3},{%4,%5,%6,%7},{%8,%9},{%0,%1,%2,%3};"
        : "+f"(c[0]), "+f"(c[1]), "+f"(c[2]), "+f"(c[3])
        : "r"(a[0]), "r"(a[1]), "r"(a[2]), "r"(a[3]), "r"(b0), "r"(b1));
}
__device__ __forceinline__ void split2h(float x, __half& h, __half& l) {
    h = __float2half_rn(x);
    l = __float2half_rn(x - __half2float(h));
}

__global__ void posenc_kernel(const float* __restrict__ ref, const float* __restrict__ src,
                              __half* __restrict__ p1h, __half* __restrict__ p1l,
                              __half* __restrict__ p2h, __half* __restrict__ p2l) {
    __shared__ float s[32][33];
    int img = blockIdx.y >> 2, n = blockIdx.y & 3;
    int ct = blockIdx.x >> 7, lt = blockIdx.x & 127;
    int c0 = ct * 32, l0 = lt * 32;
    int tid = threadIdx.x;
    const float* inp = (img == 0) ? ref : src;
#pragma unroll
    for (int p = 0; p < 4; p++) {
        int c = p * 8 + (tid >> 5), l = tid & 31;
        s[c][l] = inp[((size_t)n * DMOD + c0 + c) * LSEQ + l0 + l];
    }
    __syncthreads();
#pragma unroll
    for (int p = 0; p < 4; p++) {
        int l = p * 8 + (tid >> 5), c = tid & 31;
        int cg = c0 + c, lg = l0 + l;
        int ii = cg >> 2, jj = cg & 3;
        float dv = __expf(-(float)ii * (logf(10000.0f) / 64.0f));
        int w = lg & 63, hh = lg >> 6;
        float arg = (jj < 2 ? (float)w : (float)hh) * dv;
        float pe = (jj & 1) ? cosf(arg) : sinf(arg);
        float val = s[c][l] + pe;
        size_t o1 = ((size_t)(img * 4 + n) * LSEQ + lg) * DMOD + cg;
        size_t o2 = ((size_t)((1 - img) * 4 + n) * LSEQ + lg) * DMOD + cg;
        __half h, lo;
        split2h(val, h, lo);
        p1h[o1] = h; p1l[o1] = lo;
        p2h[o2] = h; p2l[o2] = lo;
    }
}

__global__ void wconv_all(const float* __restrict__ Wq, const float* __restrict__ Wk,
                          const float* __restrict__ Wv, const float* __restrict__ Wo,
                          const float* __restrict__ W1, const float* __restrict__ W2,
                          const float* __restrict__ bq, const float* __restrict__ bk,
                          const float* __restrict__ bv) {
    __shared__ float s[32][33];
    int li = blockIdx.x >> 9;
    int r  = blockIdx.x & 511;
    if (blockIdx.x < 4 && threadIdx.x < 256) {
        g_bqkv[blockIdx.x * QKVN + threadIdx.x]       = bq[blockIdx.x * DMOD + threadIdx.x];
        g_bqkv[blockIdx.x * QKVN + 256 + threadIdx.x] = bk[blockIdx.x * DMOD + threadIdx.x];
        g_bqkv[blockIdx.x * QKVN + 512 + threadIdx.x] = bv[blockIdx.x * DMOD + threadIdx.x];
    }
    const float* src;
    size_t dsto;
    int K, N, n0, k0;
    if (r < 256) {
        int mat = r >> 6, t = r & 63;
        K = 256; N = 256;
        n0 = (t & 7) * 32; k0 = (t >> 3) * 32;
        const float* bases[4] = {Wq, Wk, Wv, Wo};
        src  = bases[mat] + (size_t)li * 65536;
        dsto = (size_t)li * WLAYER + (size_t)mat * 65536;
    } else if (r < 384) {
        int t = r - 256;
        K = 256; N = 512;
        n0 = (t & 15) * 32; k0 = (t >> 4) * 32;
        src  = W1 + (size_t)li * 131072;
        dsto = (size_t)li * WLAYER + 262144;
    } else {
        int t = r - 384;
        K = 512; N = 256;
        n0 = (t & 7) * 32; k0 = (t >> 3) * 32;
        src  = W2 + (size_t)li * 131072;
        dsto = (size_t)li * WLAYER + 393216;
    }
    int tid = threadIdx.x;
#pragma unroll
    for (int p = 0; p < 4; p++) {
        int kk = p * 8 + (tid >> 5), nn = tid & 31;
        s[kk][nn] = src[(size_t)(k0 + kk) * N + n0 + nn];
    }
    __syncthreads();
#pragma unroll
    for (int p = 0; p < 4; p++) {
        int nn = p * 8 + (tid >> 5), kk = tid & 31;
        g_wth[dsto + (size_t)(n0 + nn) * K + k0 + kk] = __float2half_rn(s[kk][nn]);
    }
}

// ---------------- gemm_hp: 128x128 tile, 256 threads, 2 CTAs/SM -----------------
// A pair selected per CTA: cols < 256 use (Ah,Al), cols >= 256 use (A2h,A2l).
// mode: 2 = half-pair + relu; 3 = fp32 out, elu+1 on cols < 512.
__device__ __forceinline__ void load_stage(const __half* Ah, const __half* Al,
                                           const __half* Bh,
                                           int bm, int bn, int K, int k0,
                                           uint32_t sb, int tid) {
#pragma unroll
    for (int it = 0; it < 4; it++) {
        int c = tid + it * 256;
        int r = c >> 3, seg = c & 7;
        uint32_t d = swz128((uint32_t)(r * 128 + seg * 16));
        size_t ga = (size_t)(bm + r) * K + k0 + seg * 8;
        size_t gb = (size_t)(bn + r) * K + k0 + seg * 8;
        cpa16(sb + d,         Ah + ga);
        cpa16(sb + 16384 + d, Al + ga);
        cpa16(sb + 32768 + d, Bh + gb);
    }
    asm volatile("cp.async.commit_group;" ::: "memory");
}

__global__ __launch_bounds__(256, 2)
void gemm_hp(const __half* __restrict__ Ah, const __half* __restrict__ Al,
             const __half* __restrict__ A2h, const __half* __restrict__ A2l,
             const __half* __restrict__ Bh,
             const float* __restrict__ bias,
             float* __restrict__ Cf, __half* __restrict__ Ch, __half* __restrict__ Cl,
             int M, int N, int K, int mode) {
    extern __shared__ char smem[];
    uint32_t sb = smem_u32(smem);
    int tid = threadIdx.x, lane = tid & 31, warp = tid >> 5;
    int wm = warp >> 1, wn = warp & 1;
    int bm = blockIdx.y * 128, bn = blockIdx.x * 128;

    const __half* pAh = (bn < 256) ? Ah : A2h;
    const __half* pAl = (bn < 256) ? Al : A2l;

    float acc[2][8][4];
#pragma unroll
    for (int i = 0; i < 2; i++)
#pragma unroll
        for (int j = 0; j < 8; j++)
#pragma unroll
            for (int r = 0; r < 4; r++) acc[i][j][r] = 0.0f;

    const int KT = K >> 6;
    load_stage(pAh, pAl, Bh, bm, bn, K, 0, sb, tid);

    int lrow = (lane & 7) + ((lane >> 3) & 1) * 8;
    int kseg = (lane >> 4) * 16;

    for (int kt = 0; kt < KT; kt++) {
        asm volatile("cp.async.wait_group 0;" ::: "memory");
        __syncthreads();
        if (kt + 1 < KT)
            load_stage(pAh, pAl, Bh, bm, bn, K, (kt + 1) << 6, sb + ((kt + 1) & 1) * STG, tid);

        uint32_t offA = sb + (kt & 1) * STG;
        uint32_t offAl = offA + 16384, offB = offA + 32768;
#pragma unroll
        for (int kk = 0; kk < 4; kk++) {
            int kb = kk * 32 + kseg;
            uint32_t ah[2][4], al[2][4], bfr[4][4];
#pragma unroll
            for (int mt = 0; mt < 2; mt++) {
                uint32_t off = swz128((uint32_t)((wm * 32 + mt * 16 + lrow) * 128 + kb));
                ldsm4(ah[mt], offA  + off);
                ldsm4(al[mt], offAl + off);
            }
#pragma unroll
            for (int j = 0; j < 4; j++) {
                uint32_t off = swz128((uint32_t)((wn * 64 + j * 16 + lrow) * 128 + kb));
                ldsm4(bfr[j], offB + off);
            }
#pragma unroll
            for (int mt = 0; mt < 2; mt++)
#pragma unroll
                for (int j = 0; j < 4; j++)
#pragma unroll
                    for (int s = 0; s < 2; s++) {
                        int n8 = j * 2 + s;
                        mma16816(acc[mt][n8], ah[mt], bfr[j][s], bfr[j][2 + s]);
                        mma16816(acc[mt][n8], al[mt], bfr[j][s], bfr[j][2 + s]);
                    }
        }
    }
    __syncthreads();

    int gid = lane >> 2, tig = lane & 3;
#pragma unroll
    for (int n8 = 0; n8 < 8; n8++) {
        int col = bn + wn * 64 + n8 * 8 + tig * 2;
        float2 bv = *(const float2*)(bias + col);
        bool elu = (mode == 3 && col < 512);
#pragma unroll
        for (int mt = 0; mt < 2; mt++) {
            int row0 = bm + wm * 32 + mt * 16 + gid;
#pragma unroll
            for (int half = 0; half < 2; half++) {
                int row = row0 + half * 8;
                float v0 = acc[mt][n8][half * 2 + 0] + bv.x;
                float v1 = acc[mt][n8][half * 2 + 1] + bv.y;
                if (elu) {
                    v0 = (v0 > 0.f) ? v0 + 1.f : __expf(v0);
                    v1 = (v1 > 0.f) ? v1 + 1.f : __expf(v1);
                } else if (mode == 2) {
                    v0 = fmaxf(v0, 0.f);
                    v1 = fmaxf(v1, 0.f);
                }
                if (mode == 2) {
                    __half h0, l0, h1, l1;
                    split2h(v0, h0, l0);
                    split2h(v1, h1, l1);
                    *(__half2*)(Ch + (size_t)row * N + col) = __halves2half2(h0, h1);
                    *(__half2*)(Cl + (size_t)row * N + col) = __halves2half2(l0, l1);
                } else {
                    *(float2*)(Cf + (size_t)row * N + col) = make_float2(v0, v1);
                }
            }
        }
    }
}

// ---------------- gemm_ln: 128x256 tile, fused bias+residual+LayerNorm ----------
__device__ __forceinline__ void load_stage_ln(const __half* Ah, const __half* Al,
                                              const __half* Bh,
                                              int bm, int K, int k0,
                                              uint32_t sb, int tid) {
    {
        int r = tid >> 3, seg = tid & 7;
        uint32_t d = swz128((uint32_t)(r * 128 + seg * 16));
        size_t ga = (size_t)(bm + r) * K + k0 + seg * 8;
        cpa16(sb + d,         Ah + ga);
        cpa16(sb + 16384 + d, Al + ga);
    }
#pragma unroll
    for (int it = 0; it < 2; it++) {
        int c = tid + it * 1024;
        int r = c >> 3, seg = c & 7;
        uint32_t d = swz128((uint32_t)(r * 128 + seg * 16));
        cpa16(sb + 32768 + d, Bh + (size_t)r * K + k0 + seg * 8);
    }
    asm volatile("cp.async.commit_group;" ::: "memory");
}

__global__ __launch_bounds__(1024, 1)
void gemm_ln(const __half* __restrict__ Ah, const __half* __restrict__ Al,
             const __half* __restrict__ Bh,
             const float* __restrict__ bias,
             const __half* __restrict__ Rh, const __half* __restrict__ Rl,
             const float* __restrict__ gamma, const float* __restrict__ beta,
             __half* __restrict__ Oh, __half* __restrict__ Ol,
             int K) {
    extern __shared__ char smem[];
    uint32_t sb = smem_u32(smem);
    float* redS = (float*)(smem + 3 * STG2);
    float* redQ = (float*)(smem + 3 * STG2 + 2048);
    int tid = threadIdx.x, lane = tid & 31, warp = tid >> 5;
    int wm = warp >> 2, wn = warp & 3;
    int bm = blockIdx.x * 128;

    float acc[8][4];
#pragma unroll
    for (int j = 0; j < 8; j++)
#pragma unroll
        for (int r = 0; r < 4; r++) acc[j][r] = 0.0f;

    const int KT = K >> 6;
    load_stage_ln(Ah, Al, Bh, bm, K, 0, sb, tid);
    if (KT > 1) load_stage_ln(Ah, Al, Bh, bm, K, 64, sb + STG2, tid);

    int lrow = (lane & 7) + ((lane >> 3) & 1) * 8;
    int kseg = (lane >> 4) * 16;

    for (int kt = 0; kt < KT; kt++) {
        if (kt + 1 < KT) asm volatile("cp.async.wait_group 1;" ::: "memory");
        else             asm volatile("cp.async.wait_group 0;" ::: "memory");
        __syncthreads();
        if (kt + 2 < KT)
            load_stage_ln(Ah, Al, Bh, bm, K, (kt + 2) << 6, sb + ((kt + 2) % 3) * STG2, tid);

        uint32_t offA = sb + (kt % 3) * STG2;
        uint32_t offAl = offA + 16384, offB = offA + 32768;
#pragma unroll
        for (int kk = 0; kk < 4; kk++) {
            int kb = kk * 32 + kseg;
            uint32_t ah[4], al[4];
            {
                uint32_t off = swz128((uint32_t)((wm * 16 + lrow) * 128 + kb));
                ldsm4(ah, offA  + off);
                ldsm4(al, offAl + off);
            }
#pragma unroll
            for (int j = 0; j < 4; j++) {
                uint32_t bfr[4];
                uint32_t off = swz128((uint32_t)((wn * 64 + j * 16 + lrow) * 128 + kb));
                ldsm4(bfr, offB + off);
#pragma unroll
                for (int s = 0; s < 2; s++) {
                    int n8 = j * 2 + s;
                    mma16816(acc[n8], ah, bfr[s], bfr[2 + s]);
                    mma16816(acc[n8], al, bfr[s], bfr[2 + s]);
                }
            }
        }
    }
    __syncthreads();

    int gid = lane >> 2, tig = lane & 3;
    float s0 = 0.f, q0 = 0.f, s1 = 0.f, q1 = 0.f;
#pragma unroll
    for (int n8 = 0; n8 < 8; n8++) {
        int col = wn * 64 + n8 * 8 + tig * 2;
        float2 bv = *(const float2*)(bias + col);
#pragma unroll
        for (int half = 0; half < 2; half++) {
            int row = bm + wm * 16 + gid + half * 8;
            __half2 rh = *(const __half2*)(Rh + (size_t)row * DMOD + col);
            __half2 rl = *(const __half2*)(Rl + (size_t)row * DMOD + col);
            float v0 = acc[n8][half * 2 + 0] + bv.x + __half2float(rh.x) + __half2float(rl.x);
            float v1 = acc[n8][half * 2 + 1] + bv.y + __half2float(rh.y) + __half2float(rl.y);
            acc[n8][half * 2 + 0] = v0;
            acc[n8][half * 2 + 1] = v1;
            if (half == 0) { s0 += v0 + v1; q0 += v0 * v0 + v1 * v1; }
            else           { s1 += v0 + v1; q1 += v0 * v0 + v1 * v1; }
        }
    }
#pragma unroll
    for (int o = 1; o < 4; o <<= 1) {
        s0 += __shfl_xor_sync(0xffffffffu, s0, o);
        q0 += __shfl_xor_sync(0xffffffffu, q0, o);
        s1 += __shfl_xor_sync(0xffffffffu, s1, o);
        q1 += __shfl_xor_sync(0xffffffffu, q1, o);
    }
    if (tig == 0) {
        int r0 = wm * 16 + gid;
        redS[r0 * 4 + wn] = s0;       redQ[r0 * 4 + wn] = q0;
        redS[(r0 + 8) * 4 + wn] = s1; redQ[(r0 + 8) * 4 + wn] = q1;
    }
    __syncthreads();

    int r0 = wm * 16 + gid;
    float ts0 = redS[r0 * 4 + 0] + redS[r0 * 4 + 1] + redS[r0 * 4 + 2] + redS[r0 * 4 + 3];
    float tq0 = redQ[r0 * 4 + 0] + redQ[r0 * 4 + 1] + redQ[r0 * 4 + 2] + redQ[r0 * 4 + 3];
    int r1 = r0 + 8;
    float ts1 = redS[r1 * 4 + 0] + redS[r1 * 4 + 1] + redS[r1 * 4 + 2] + redS[r1 * 4 + 3];
    float tq1 = redQ[r1 * 4 + 0] + redQ[r1 * 4 + 1] + redQ[r1 * 4 + 2] + redQ[r1 * 4 + 3];
    float mean0 = ts0 * (1.0f / 256.0f);
    float inv0  = rsqrtf(tq0 * (1.0f / 256.0f) - mean0 * mean0 + 1e-5f);
    float mean1 = ts1 * (1.0f / 256.0f);
    float inv1  = rsqrtf(tq1 * (1.0f / 256.0f) - mean1 * mean1 + 1e-5f);

#pragma unroll
    for (int n8 = 0; n8 < 8; n8++) {
        int col = wn * 64 + n8 * 8 + tig * 2;
        float2 gv = *(const float2*)(gamma + col);
        float2 be = *(const float2*)(beta + col);
#pragma unroll
        for (int half = 0; half < 2; half++) {
            int row = bm + wm * 16 + gid + half * 8;
            float mean = half ? mean1 : mean0;
            float inv  = half ? inv1  : inv0;
            float v0 = (acc[n8][half * 2 + 0] - mean) * inv * gv.x + be.x;
            float v1 = (acc[n8][half * 2 + 1] - mean) * inv * gv.y + be.y;
            __half h0, l0, h1, l1;
            split2h(v0, h0, l0);
            split2h(v1, h1, l1);
            *(__half2*)(Oh + (size_t)row * DMOD + col) = __halves2half2(h0, h1);
            *(__half2*)(Ol + (size_t)row * DMOD + col) = __halves2half2(l0, l1);
        }
    }
}

// ---------------- KV partial over combined [M,768] buffer -----------------------
__global__ void kv_partial(const float* __restrict__ QKV,
                           float* __restrict__ KVp, float* __restrict__ Ksp) {
    int blk = blockIdx.x;
    int bh = blk >> 4, ch = blk & (KVCH - 1);
    int b = bh >> 3, h = bh & 7;
    int tid = threadIdx.x;
    __shared__ float Ks[32][36];
    __shared__ float Vs[32][32];
    int m = tid >> 3, d0 = (tid & 7) * 4;
    float acc[4] = {0.f, 0.f, 0.f, 0.f};
    float ks[4]  = {0.f, 0.f, 0.f, 0.f};
    int lr = tid >> 3, lc = (tid & 7) * 4;
    int lbeg = ch * (LSEQ / KVCH), lend = lbeg + (LSEQ / KVCH);
    for (int l0 = lbeg; l0 < lend; l0 += 32) {
        size_t base = ((size_t)(b * LSEQ + l0 + lr)) * QKVN + 256 + h * HDIM + lc;
        float4 kv4 = *(const float4*)(QKV + base);
        float4 vv4 = *(const float4*)(QKV + base + 256);
        Ks[lr][lc + 0] = kv4.x; Ks[lr][lc + 1] = kv4.y;
        Ks[lr][lc + 2] = kv4.z; Ks[lr][lc + 3] = kv4.w;
        *(float4*)&Vs[lr][lc] = vv4;
        __syncthreads();
#pragma unroll 8
        for (int r = 0; r < 32; r++) {
            float vm = Vs[r][m];
#pragma unroll
            for (int j = 0; j < 4; j++) acc[j] = fmaf(vm, Ks[r][d0 + j], acc[j]);
            if (m == 0) {
#pragma unroll
                for (int j = 0; j < 4; j++) ks[j] += Ks[r][d0 + j];
            }
        }
        __syncthreads();
    }
    size_t obase = ((size_t)blk * HDIM + m) * HDIM + d0;
#pragma unroll
    for (int j = 0; j < 4; j++) KVp[obase + j] = acc[j];
    if (m == 0) {
#pragma unroll
        for (int j = 0; j < 4; j++) Ksp[blk * HDIM + d0 + j] = ks[j];
    }
}

__global__ void kv_finalize(const float* __restrict__ KVp, const float* __restrict__ Ksp,
                            float* __restrict__ KV, float* __restrict__ Ksum) {
    int bh = blockIdx.x, tid = threadIdx.x;
#pragma unroll
    for (int o = 0; o < 4; o++) {
        int idx = tid + o * 256;
        float s = 0.f;
#pragma unroll
        for (int c = 0; c < KVCH; c++)
            s += KVp[((size_t)(bh * KVCH + c)) * (HDIM * HDIM) + idx];
        KV[(size_t)bh * (HDIM * HDIM) + idx] = s;
    }
    if (tid < HDIM) {
        float s = 0.f;
#pragma unroll
        for (int c = 0; c < KVCH; c++)
            s += Ksp[(bh * KVCH + c) * HDIM + tid];
        Ksum[bh * HDIM + tid] = s;
    }
}

__global__ void attn_apply(const float* __restrict__ QKV, const float* __restrict__ KV,
                           const float* __restrict__ Ksum,
                           __half* __restrict__ Mh, __half* __restrict__ Ml) {
    int blk = blockIdx.x;
    int b = blk >> 5, lt = (blk & 31) * 128;
    int tid = threadIdx.x;
    __shared__ float KVs[NHEAD * HDIM * 33];
    __shared__ float Ksums[NHEAD * HDIM];
    for (int i = tid; i < NHEAD * HDIM * HDIM; i += 256) {
        int h = i >> 10, m = (i >> 5) & 31, d = i & 31;
        KVs[(h * HDIM + m) * 33 + d] = KV[((size_t)(b * NHEAD + h) * HDIM + m) * HDIM + d];
    }
    for (int i = tid; i < NHEAD * HDIM; i += 256)
        Ksums[i] = Ksum[b * NHEAD * HDIM + i];
    __syncthreads();
    int h = tid >> 5, m = tid & 31;
    const float* kvrow = &KVs[(h * HDIM + m) * 33];
    const float* ksr   = &Ksums[h * HDIM];
    for (int r = 0; r < 128; r++) {
        int l = lt + r;
        const float* q = QKV + ((size_t)(b * LSEQ + l)) * QKVN + h * HDIM;
        float num = 0.f, den = 0.f;
#pragma unroll
        for (int d = 0; d < HDIM; d += 4) {
            float4 qv = *(const float4*)(q + d);
            num = fmaf(qv.x, kvrow[d],     num);
            num = fmaf(qv.y, kvrow[d + 1], num);
            num = fmaf(qv.z, kvrow[d + 2], num);
            num = fmaf(qv.w, kvrow[d + 3], num);
            den = fmaf(qv.x, ksr[d],     den);
            den = fmaf(qv.y, ksr[d + 1], den);
            den = fmaf(qv.z, ksr[d + 2], den);
            den = fmaf(qv.w, ksr[d + 3], den);
        }
        float o = num / (den + 1e-6f);
        __half hh, ll;
        split2h(o, hh, ll);
        size_t oi = ((size_t)(b * LSEQ + l)) * DMOD + tid;
        Mh[oi] = hh; Ml[oi] = ll;
    }
}

__global__ void write_out(const __half* __restrict__ Xh, const __half* __restrict__ Xl,
                          float* __restrict__ out) {
    __shared__ float s[32][33];
    int n  = blockIdx.y;
    int ct = blockIdx.x >> 7, lt = blockIdx.x & 127;
    int c0 = ct * 32, l0 = lt * 32;
    int tid = threadIdx.x;
#pragma unroll
    for (int p = 0; p < 4; p++) {
        int l = p * 8 + (tid >> 5), c = tid & 31;
        size_t idx = ((size_t)n * LSEQ + l0 + l) * DMOD + c0 + c;
        s[l][c] = __half2float(Xh[idx]) + __half2float(Xl[idx]);
    }
    __syncthreads();
#pragma unroll
    for (int p = 0; p < 4; p++) {
        int c = p * 8 + (tid >> 5), l = tid & 31;
        out[((size_t)n * DMOD + c0 + c) * LSEQ + l0 + l] = s[l][c];
    }
}

extern "C" void kernel_launch(void* const* d_in, const int* in_sizes, int n_in,
                              void* d_out, int out_size) {
    const float* ref = (const float*)d_in[0];
    const float* src = (const float*)d_in[1];
    const float* Wq  = (const float*)d_in[2];
    const float* bq  = (const float*)d_in[3];
    const float* Wk  = (const float*)d_in[4];
    const float* bk  = (const float*)d_in[5];
    const float* Wv  = (const float*)d_in[6];
    const float* bv  = (const float*)d_in[7];
    const float* Wo  = (const float*)d_in[8];
    const float* bo  = (const float*)d_in[9];
    const float* W1  = (const float*)d_in[10];
    const float* b1  = (const float*)d_in[11];
    const float* W2  = (const float*)d_in[12];
    const float* b2  = (const float*)d_in[13];
    const float* G1  = (const float*)d_in[14];
    const float* Be1 = (const float*)d_in[15];
    const float* G2  = (const float*)d_in[16];
    const float* Be2 = (const float*)d_in[17];

    float *qkv, *kv, *ks, *kvp, *ksp, *bqkv;
    __half *xh, *xl, *p2h, *p2l, *mh, *ml, *hh, *hl, *wth;
    cudaGetSymbolAddress((void**)&qkv,  g_qkv);
    cudaGetSymbolAddress((void**)&kv,   g_kv);
    cudaGetSymbolAddress((void**)&ks,   g_ks);
    cudaGetSymbolAddress((void**)&kvp,  g_kvp);
    cudaGetSymbolAddress((void**)&ksp,  g_ksp);
    cudaGetSymbolAddress((void**)&bqkv, g_bqkv);
    cudaGetSymbolAddress((void**)&xh,   g_xh);
    cudaGetSymbolAddress((void**)&xl,   g_xl);
    cudaGetSymbolAddress((void**)&p2h,  g_p2h);
    cudaGetSymbolAddress((void**)&p2l,  g_p2l);
    cudaGetSymbolAddress((void**)&mh,   g_mh);
    cudaGetSymbolAddress((void**)&ml,   g_ml);
    cudaGetSymbolAddress((void**)&hh,   g_hh);
    cudaGetSymbolAddress((void**)&hl,   g_hl);
    cudaGetSymbolAddress((void**)&wth,  g_wth);

    cudaFuncSetAttribute(gemm_hp, cudaFuncAttributeMaxDynamicSharedMemorySize, GSMEM);
    cudaFuncSetAttribute(gemm_ln, cudaFuncAttributeMaxDynamicSharedMemorySize, GSMEM_LN);

    wconv_all<<<2048, 256>>>(Wq, Wk, Wv, Wo, W1, W2, bq, bk, bv);
    {
        dim3 pb(8 * 128, 8);
        posenc_kernel<<<pb, 256>>>(ref, src, xh, xl, p2h, p2l);
    }

    dim3 gqkv(6, MROWS / 128);   // N=768
    dim3 g512(4, MROWS / 128);   // N=512

    for (int li = 0; li < 4; li++) {
        size_t wl  = (size_t)li * WLAYER;
        size_t bo_ = (size_t)li * DMOD;
        size_t b1o = (size_t)li * DFF;
        const __half* sh = (li % 2 == 0) ? xh : p2h;
        const __half* sl = (li % 2 == 0) ? xl : p2l;

        // combined Q|K|V projection: cols 0-255 from x (q), cols 256-767 from s (k,v)
        gemm_hp<<<gqkv, 256, GSMEM>>>(xh, xl, sh, sl, wth + wl + 0,
                                      bqkv + (size_t)li * QKVN, qkv, 0, 0,
                                      MROWS, QKVN, DMOD, 3);

        kv_partial<<<BATCH * NHEAD * KVCH, 256>>>(qkv, kvp, ksp);
        kv_finalize<<<BATCH * NHEAD, 256>>>(kvp, ksp, kv, ks);
        attn_apply<<<BATCH * 32, 256>>>(qkv, kv, ks, mh, ml);

        gemm_ln<<<MROWS / 128, 1024, GSMEM_LN>>>(mh, ml, wth + wl + 196608, bo + bo_,
                                                 xh, xl, G1 + bo_, Be1 + bo_, xh, xl, DMOD);

        gemm_hp<<<g512, 256, GSMEM>>>(xh, xl, xh, xl, wth + wl + 262144, b1 + b1o,
                                      0, hh, hl, MROWS, DFF, DMOD, 2);

        gemm_ln<<<MROWS / 128, 1024, GSMEM_LN>>>(hh, hl, wth + wl + 393216, b2 + bo_,
                                                 xh, xl, G2 + bo_, Be2 + bo_, xh, xl, DFF);
    }

    {
        dim3 wb(8 * 128, 8);
        write_out<<<wb, 256>>>(xh, xl, (float*)d_out);
    }
}